// round 16
// baseline (speedup 1.0000x reference)
#include <cuda_runtime.h>
#include <cuda_bf16.h>
#include <cuda_fp16.h>
#include <math.h>
#include <stdint.h>

#define BATCH 2
#define SEQ   2048
#define DIM   1024
#define NH    16
#define HD    64
#define QKV_OFF (BATCH * NH * SEQ * HD)

// Scratch (allocation-free)
__device__ float g_qkv[3 * QKV_OFF];            // Q, K, V (pre-RoPE) in [B,H,S,HD]
__device__ float g_cos[SEQ * 32];
__device__ float g_sin[SEQ * 32];
__device__ __half g_a_hi[BATCH * SEQ * DIM];    // fp16 hi/lo split activations
__device__ __half g_a_lo[BATCH * SEQ * DIM];
__device__ __half g_wt_hi[3 * DIM * DIM];       // fp16 hi/lo split weights [N,K]
__device__ __half g_wt_lo[3 * DIM * DIM];

// ---------------------------------------------------------------------------
__device__ __forceinline__ uint32_t smem_u32(const void* p) {
    uint32_t a;
    asm("{ .reg .u64 t; cvta.to.shared.u64 t, %1; cvt.u32.u64 %0, t; }"
        : "=r"(a) : "l"(p));
    return a;
}

__device__ __forceinline__ void cpa16(uint32_t saddr, const void* g) {
    asm volatile("cp.async.cg.shared.global [%0], [%1], 16;" :: "r"(saddr), "l"(g));
}
#define CPA_COMMIT() asm volatile("cp.async.commit_group;" ::: "memory")
#define CPA_WAIT1()  asm volatile("cp.async.wait_group 1;" ::: "memory")

__device__ __forceinline__ void ldsm_x4(uint32_t* r, uint32_t addr) {
    asm volatile("ldmatrix.sync.aligned.m8n8.x4.shared.b16 {%0,%1,%2,%3}, [%4];"
                 : "=r"(r[0]), "=r"(r[1]), "=r"(r[2]), "=r"(r[3]) : "r"(addr));
}

// bf16 split (attention internals)
__device__ __forceinline__ void split2(float x, __nv_bfloat16& h, __nv_bfloat16& l) {
    h = __float2bfloat16(x);
    l = __float2bfloat16(x - __bfloat162float(h));
}

__device__ __forceinline__ uint32_t pack_hi_split(float x, float y, uint32_t* lo_out) {
    __nv_bfloat16 hx = __float2bfloat16(x);
    __nv_bfloat16 hy = __float2bfloat16(y);
    __nv_bfloat16 lx = __float2bfloat16(x - __bfloat162float(hx));
    __nv_bfloat16 ly = __float2bfloat16(y - __bfloat162float(hy));
    *lo_out = (uint32_t)__bfloat16_as_ushort(lx) | ((uint32_t)__bfloat16_as_ushort(ly) << 16);
    return (uint32_t)__bfloat16_as_ushort(hx) | ((uint32_t)__bfloat16_as_ushort(hy) << 16);
}

__device__ __forceinline__ void mma_bf16(float* c, const uint32_t* a, const uint32_t* b) {
    asm volatile("mma.sync.aligned.m16n8k16.row.col.f32.bf16.bf16.f32 "
                 "{%0,%1,%2,%3}, {%4,%5,%6,%7}, {%8,%9}, {%0,%1,%2,%3};"
                 : "+f"(c[0]), "+f"(c[1]), "+f"(c[2]), "+f"(c[3])
                 : "r"(a[0]), "r"(a[1]), "r"(a[2]), "r"(a[3]), "r"(b[0]), "r"(b[1]));
}

__device__ __forceinline__ void mma_f16(float* c, const uint32_t* a, const uint32_t* b) {
    asm volatile("mma.sync.aligned.m16n8k16.row.col.f32.f16.f16.f32 "
                 "{%0,%1,%2,%3}, {%4,%5,%6,%7}, {%8,%9}, {%0,%1,%2,%3};"
                 : "+f"(c[0]), "+f"(c[1]), "+f"(c[2]), "+f"(c[3])
                 : "r"(a[0]), "r"(a[1]), "r"(a[2]), "r"(a[3]), "r"(b[0]), "r"(b[1]));
}

// fp16 split (projection path)
__device__ __forceinline__ void split2h(float x, __half& h, __half& l) {
    h = __float2half(x);
    l = __float2half(x - __half2float(h));
}

// activations: fp32 [R,1024] -> hi/lo fp16 same layout
__global__ __launch_bounds__(256) void convert_act_kernel(const float* __restrict__ in,
                                                          __half* __restrict__ hi,
                                                          __half* __restrict__ lo) {
    const int i4 = (blockIdx.x * 256 + threadIdx.x) * 4;
    const float4 v = *(const float4*)(in + i4);
    __half h0, h1, h2, h3, l0, l1, l2, l3;
    split2h(v.x, h0, l0); split2h(v.y, h1, l1);
    split2h(v.z, h2, l2); split2h(v.w, h3, l3);
    *(__half2*)(hi + i4)     = __halves2half2(h0, h1);
    *(__half2*)(hi + i4 + 2) = __halves2half2(h2, h3);
    *(__half2*)(lo + i4)     = __halves2half2(l0, l1);
    *(__half2*)(lo + i4 + 2) = __halves2half2(l2, l3);
}

// weights: fp32 W[K,N] -> transposed hi/lo fp16 [N,K]; blockIdx.z picks W
__global__ __launch_bounds__(256) void convert_wt_kernel(const float* __restrict__ W0,
                                                         const float* __restrict__ W1,
                                                         const float* __restrict__ W2,
                                                         __half* __restrict__ thi,
                                                         __half* __restrict__ tlo) {
    __shared__ float t[32][33];
    const int z = blockIdx.z;
    const float* W = (z == 0) ? W0 : ((z == 1) ? W1 : W2);
    const size_t zo = (size_t)z * DIM * DIM;
    const int tx = threadIdx.x, ty = threadIdx.y;           // (32, 8)
    const int n0 = blockIdx.x * 32, k0 = blockIdx.y * 32;
#pragma unroll
    for (int j = 0; j < 4; j++)
        t[ty + 8 * j][tx] = W[(size_t)(k0 + ty + 8 * j) * DIM + n0 + tx];
    __syncthreads();
#pragma unroll
    for (int j = 0; j < 4; j++) {
        const int n = n0 + ty + 8 * j;
        const float x = t[tx][ty + 8 * j];
        __half h, l;
        split2h(x, h, l);
        thi[zo + (size_t)n * DIM + k0 + tx] = h;
        tlo[zo + (size_t)n * DIM + k0 + tx] = l;
    }
}

// ---------------------------------------------------------------------------
// Split-fp16 tensor-core GEMM, cp.async double-buffered + ldmatrix.
// Q,K (z<2, HEADS_OUT): 3 products. V (z==2) and out-proj: 2 products
// (ah*bh + ah*bl), skipping all Alo traffic.
// ---------------------------------------------------------------------------
#define SSTR 40
#define TILEB (128 * SSTR * 2)
#define BUFB  (4 * TILEB)
#define GSMEM (2 * BUFB)

template <int HEADS_OUT>
__global__ __launch_bounds__(256) void gemm_mma_kernel(
    const __half* __restrict__ Ahi, const __half* __restrict__ Alo,
    const __half* __restrict__ Bhi, const __half* __restrict__ Blo,
    float* __restrict__ O) {
    extern __shared__ __align__(16) char dsm[];
    const uint32_t sb = smem_u32(dsm);

    const int tid = threadIdx.x;
    const int wid = tid >> 5, lane = tid & 31;
    const int gid = lane >> 2, tig = lane & 3;
    const int warp_m = wid >> 2, warp_n = wid & 3;
    const int m0 = blockIdx.y * 128, n0 = blockIdx.x * 128;
    const size_t wz = (size_t)blockIdx.z * DIM * DIM;
    float* Oz = O + (size_t)blockIdx.z * QKV_OFF;
    const bool p3 = HEADS_OUT ? (blockIdx.z < 2) : false;   // 3-product for Q,K only

    const uint32_t lmrow = (lane & 7) + ((lane >> 3) & 1) * 8;
    const uint32_t lmk   = (lane >> 4) * 8;

    float acc[4][4][4];
#pragma unroll
    for (int i = 0; i < 4; i++)
#pragma unroll
        for (int j = 0; j < 4; j++)
#pragma unroll
            for (int r = 0; r < 4; r++) acc[i][j][r] = 0.f;

    const int lrow = tid >> 1;
    const int lkc  = (tid & 1) * 16;
    const uint32_t so = (uint32_t)(lrow * SSTR + lkc) * 2;

    {
        const size_t ga = (size_t)(m0 + lrow) * DIM + lkc;
        const size_t gb = wz + (size_t)(n0 + lrow) * DIM + lkc;
        const uint32_t b0 = sb;
        cpa16(b0 + 0 * TILEB + so,      Ahi + ga);
        cpa16(b0 + 0 * TILEB + so + 16, Ahi + ga + 8);
        if (p3) {
            cpa16(b0 + 1 * TILEB + so,      Alo + ga);
            cpa16(b0 + 1 * TILEB + so + 16, Alo + ga + 8);
        }
        cpa16(b0 + 2 * TILEB + so,      Bhi + gb);
        cpa16(b0 + 2 * TILEB + so + 16, Bhi + gb + 8);
        cpa16(b0 + 3 * TILEB + so,      Blo + gb);
        cpa16(b0 + 3 * TILEB + so + 16, Blo + gb + 8);
        CPA_COMMIT();
    }

    const int T = DIM / 32;
    for (int t = 0; t < T; t++) {
        if (t + 1 < T) {
            const int k0 = (t + 1) * 32;
            const size_t ga = (size_t)(m0 + lrow) * DIM + k0 + lkc;
            const size_t gb = wz + (size_t)(n0 + lrow) * DIM + k0 + lkc;
            const uint32_t bb = sb + ((t + 1) & 1) * BUFB;
            cpa16(bb + 0 * TILEB + so,      Ahi + ga);
            cpa16(bb + 0 * TILEB + so + 16, Ahi + ga + 8);
            if (p3) {
                cpa16(bb + 1 * TILEB + so,      Alo + ga);
                cpa16(bb + 1 * TILEB + so + 16, Alo + ga + 8);
            }
            cpa16(bb + 2 * TILEB + so,      Bhi + gb);
            cpa16(bb + 2 * TILEB + so + 16, Bhi + gb + 8);
            cpa16(bb + 3 * TILEB + so,      Blo + gb);
            cpa16(bb + 3 * TILEB + so + 16, Blo + gb + 8);
        }
        CPA_COMMIT();
        CPA_WAIT1();
        __syncthreads();

        const uint32_t bufb = sb + (t & 1) * BUFB;
        const uint32_t pAh = bufb + 0 * TILEB, pAl = bufb + 1 * TILEB;
        const uint32_t pBh = bufb + 2 * TILEB, pBl = bufb + 3 * TILEB;

#pragma unroll
        for (int kk = 0; kk < 32; kk += 16) {
            uint32_t bh[4][2], bl[4][2], t4[4];
#pragma unroll
            for (int p = 0; p < 2; p++) {
                const uint32_t off =
                    (uint32_t)((warp_n * 32 + p * 16 + lmrow) * SSTR + kk + lmk) * 2;
                ldsm_x4(t4, pBh + off);
                bh[2 * p][0] = t4[0]; bh[2 * p + 1][0] = t4[1];
                bh[2 * p][1] = t4[2]; bh[2 * p + 1][1] = t4[3];
                ldsm_x4(t4, pBl + off);
                bl[2 * p][0] = t4[0]; bl[2 * p + 1][0] = t4[1];
                bl[2 * p][1] = t4[2]; bl[2 * p + 1][1] = t4[3];
            }
#pragma unroll
            for (int mt = 0; mt < 4; mt++) {
                const uint32_t off =
                    (uint32_t)((warp_m * 64 + mt * 16 + lmrow) * SSTR + kk + lmk) * 2;
                uint32_t ah[4], al[4];
                ldsm_x4(ah, pAh + off);
                if (p3) ldsm_x4(al, pAl + off);
#pragma unroll
                for (int nt = 0; nt < 4; nt++) mma_f16(acc[mt][nt], ah, bh[nt]);
#pragma unroll
                for (int nt = 0; nt < 4; nt++) mma_f16(acc[mt][nt], ah, bl[nt]);
                if (p3) {
#pragma unroll
                    for (int nt = 0; nt < 4; nt++) mma_f16(acc[mt][nt], al, bh[nt]);
                }
            }
        }
        __syncthreads();
    }

#pragma unroll
    for (int mt = 0; mt < 4; mt++) {
#pragma unroll
        for (int nt = 0; nt < 4; nt++) {
            const int m = m0 + warp_m * 64 + mt * 16 + gid;
            const int n = n0 + warp_n * 32 + nt * 8 + tig * 2;
            if (HEADS_OUT) {
                const int h = n >> 6, nc = n & 63;
                const int b0_ = m >> 11, s0 = m & (SEQ - 1);
                const int b1_ = (m + 8) >> 11, s1 = (m + 8) & (SEQ - 1);
                float* d0 = Oz + (((size_t)(b0_ * NH + h) * SEQ + s0) * HD) + nc;
                float* d1 = Oz + (((size_t)(b1_ * NH + h) * SEQ + s1) * HD) + nc;
                *(float2*)d0 = make_float2(acc[mt][nt][0], acc[mt][nt][1]);
                *(float2*)d1 = make_float2(acc[mt][nt][2], acc[mt][nt][3]);
            } else {
                *(float2*)&O[(size_t)m * DIM + n] =
                    make_float2(acc[mt][nt][0], acc[mt][nt][1]);
                *(float2*)&O[(size_t)(m + 8) * DIM + n] =
                    make_float2(acc[mt][nt][2], acc[mt][nt][3]);
            }
        }
    }
}

// ---------------------------------------------------------------------------
// RoPE table (exact trig of fp32-rounded angle).
// ---------------------------------------------------------------------------
__global__ __launch_bounds__(256) void rope_table_kernel() {
    const int idx = blockIdx.x * blockDim.x + threadIdx.x;
    const int d = idx & 31;
    const int t = idx >> 5;
    const float f32 = (float)pow(10000.0, -(double)d / 32.0);
    const float ang = (float)t * f32;
    double sd, cd;
    sincos((double)ang, &sd, &cd);
    g_cos[idx] = (float)cd;
    g_sin[idx] = (float)sd;
}

// ---------------------------------------------------------------------------
// Tensor-core flash attention with fused RoPE (Q at fragment build, K at
// staging) and fused fp16 hi/lo epilogue (writes out-proj A operand directly).
// ---------------------------------------------------------------------------
#define ATS 72

__global__ __launch_bounds__(256) void attn_mma_kernel(const float* __restrict__ Q,
                                                       const float* __restrict__ K,
                                                       const float* __restrict__ V,
                                                       const int* __restrict__ pos_ids,
                                                       __half* __restrict__ ahi,
                                                       __half* __restrict__ alo) {
    __shared__ __align__(16) __nv_bfloat16 sKh[64 * ATS], sKl[64 * ATS];  // [kv][dim]
    __shared__ __align__(16) __nv_bfloat16 sVh[64 * ATS], sVl[64 * ATS];  // [dim][kv]

    const int tid = threadIdx.x;
    const int wid = tid >> 5, lane = tid & 31;
    const int gid = lane >> 2, tig = lane & 3;
    const int bh = blockIdx.y;
    const int qb = blockIdx.x;
    const int q0w = qb * 128 + wid * 16;
    const int rowA = q0w + gid, rowB = rowA + 8;
    const size_t bh_base = (size_t)bh * SEQ * HD;
    const int b_ = bh >> 4, h = bh & 15;

    const uint32_t lmrow = (lane & 7) + ((lane >> 3) & 1) * 8;
    const uint32_t lmk   = (lane >> 4) * 8;
    const uint32_t pKh = smem_u32(sKh), pKl = smem_u32(sKl);
    const uint32_t pVh = smem_u32(sVh), pVl = smem_u32(sVl);

    // Q fragments: load raw Q, apply RoPE + 1/8 scale, split bf16 hi/lo
    uint32_t qh[4][4], ql[4][4];
    {
        const int posA = pos_ids[b_ * SEQ + rowA];
        const int posB = pos_ids[b_ * SEQ + rowB];
#pragma unroll
        for (int j = 0; j < 4; j++) {
#pragma unroll
            for (int r = 0; r < 4; r++) {
                const int row = (r & 1) ? rowB : rowA;
                const int pos = (r & 1) ? posB : posA;
                const int k = j * 16 + tig * 2 + ((r >> 1) ? 8 : 0);
                const int d = k & 31;
                const float2 x  = *(const float2*)(Q + bh_base + (size_t)row * HD + k);
                const float2 xo = *(const float2*)(Q + bh_base + (size_t)row * HD + (k ^ 32));
                const float c0 = g_cos[pos * 32 + d],     s0 = g_sin[pos * 32 + d];
                const float c1 = g_cos[pos * 32 + d + 1], s1 = g_sin[pos * 32 + d + 1];
                const float sgn = (k < 32) ? -1.f : 1.f;
                const float v0 = (x.x * c0 + sgn * xo.x * s0) * 0.125f;
                const float v1 = (x.y * c1 + sgn * xo.y * s1) * 0.125f;
                qh[j][r] = pack_hi_split(v0, v1, &ql[j][r]);
            }
        }
    }

    float o[8][4];
#pragma unroll
    for (int d = 0; d < 8; d++)
#pragma unroll
        for (int r = 0; r < 4; r++) o[d][r] = 0.f;
    float mrow[2] = {-1e30f, -1e30f};
    float lrow[2] = {0.f, 0.f};

    const int ntiles = 2 * qb + 2;

    for (int t = 0; t < ntiles; t++) {
        const int kv0 = t * 64;

        __syncthreads();
        {
            const int krow = tid >> 2;
            const int c0 = (tid & 3) * 16;
            const int kvrow = kv0 + krow;
            const float* Krow = K + bh_base + (size_t)kvrow * HD;
            const float4* Vg = (const float4*)(V + bh_base + (size_t)kvrow * HD + c0);
            const int posK = pos_ids[b_ * SEQ + kvrow];
            const float* ct = g_cos + posK * 32;
            const float* st = g_sin + posK * 32;
#pragma unroll
            for (int i = 0; i < 4; i++) {
                const int c = c0 + i * 4;
                const int d = c & 31;
                const float sgn = (c < 32) ? -1.f : 1.f;
                const float4 xk = *(const float4*)(Krow + c);
                const float4 xo = *(const float4*)(Krow + (c ^ 32));
                const float r0 = xk.x * ct[d]     + sgn * xo.x * st[d];
                const float r1 = xk.y * ct[d + 1] + sgn * xo.y * st[d + 1];
                const float r2 = xk.z * ct[d + 2] + sgn * xo.z * st[d + 2];
                const float r3 = xk.w * ct[d + 3] + sgn * xo.w * st[d + 3];
                uint32_t lo0, lo1;
                const uint32_t hi0 = pack_hi_split(r0, r1, &lo0);
                const uint32_t hi1 = pack_hi_split(r2, r3, &lo1);
                const int so = krow * ATS + c;
                *(uint32_t*)&sKh[so]     = hi0;
                *(uint32_t*)&sKh[so + 2] = hi1;
                *(uint32_t*)&sKl[so]     = lo0;
                *(uint32_t*)&sKl[so + 2] = lo1;

                const float4 vv = Vg[i];
                const float ve[4] = {vv.x, vv.y, vv.z, vv.w};
#pragma unroll
                for (int e = 0; e < 4; e++) {
                    const int dd = c + e;
                    __nv_bfloat16 hh, ll;
                    split2(ve[e], hh, ll);
                    sVh[dd * ATS + krow] = hh;
                    sVl[dd * ATS + krow] = ll;
                }
            }
        }
        __syncthreads();

        if (kv0 <= q0w + 15) {
            float sc[8][4];
#pragma unroll
            for (int nt = 0; nt < 8; nt++)
#pragma unroll
                for (int r = 0; r < 4; r++) sc[nt][r] = 0.f;

#pragma unroll
            for (int j = 0; j < 4; j++) {
#pragma unroll
                for (int p = 0; p < 4; p++) {
                    const uint32_t off =
                        (uint32_t)((p * 16 + lmrow) * ATS + j * 16 + lmk) * 2;
                    uint32_t th[4], tl[4];
                    ldsm_x4(th, pKh + off);
                    ldsm_x4(tl, pKl + off);
                    uint32_t b0h[2] = {th[0], th[2]}, b1h[2] = {th[1], th[3]};
                    uint32_t b0l[2] = {tl[0], tl[2]}, b1l[2] = {tl[1], tl[3]};
                    mma_bf16(sc[2 * p],     qh[j], b0h);
                    mma_bf16(sc[2 * p + 1], qh[j], b1h);
                    mma_bf16(sc[2 * p],     qh[j], b0l);
                    mma_bf16(sc[2 * p + 1], qh[j], b1l);
                    mma_bf16(sc[2 * p],     ql[j], b0h);
                    mma_bf16(sc[2 * p + 1], ql[j], b1h);
                }
            }

            if (kv0 + 63 > q0w) {
#pragma unroll
                for (int nt = 0; nt < 8; nt++) {
                    const int col = kv0 + nt * 8 + tig * 2;
                    if (col > rowA)     sc[nt][0] = -1e30f;
                    if (col + 1 > rowA) sc[nt][1] = -1e30f;
                    if (col > rowB)     sc[nt][2] = -1e30f;
                    if (col + 1 > rowB) sc[nt][3] = -1e30f;
                }
            }

            float tm0 = -1e30f, tm1 = -1e30f;
#pragma unroll
            for (int nt = 0; nt < 8; nt++) {
                tm0 = fmaxf(tm0, fmaxf(sc[nt][0], sc[nt][1]));
                tm1 = fmaxf(tm1, fmaxf(sc[nt][2], sc[nt][3]));
            }
            tm0 = fmaxf(tm0, __shfl_xor_sync(0xffffffffu, tm0, 1));
            tm0 = fmaxf(tm0, __shfl_xor_sync(0xffffffffu, tm0, 2));
            tm1 = fmaxf(tm1, __shfl_xor_sync(0xffffffffu, tm1, 1));
            tm1 = fmaxf(tm1, __shfl_xor_sync(0xffffffffu, tm1, 2));

            const float mn0 = fmaxf(mrow[0], tm0);
            const float mn1 = fmaxf(mrow[1], tm1);
            const float cr0 = __expf(mrow[0] - mn0);
            const float cr1 = __expf(mrow[1] - mn1);
            mrow[0] = mn0; mrow[1] = mn1;
            lrow[0] *= cr0; lrow[1] *= cr1;
#pragma unroll
            for (int d = 0; d < 8; d++) {
                o[d][0] *= cr0; o[d][1] *= cr0;
                o[d][2] *= cr1; o[d][3] *= cr1;
            }

            float ps0 = 0.f, ps1 = 0.f;
#pragma unroll
            for (int nt = 0; nt < 8; nt++) {
                sc[nt][0] = __expf(sc[nt][0] - mn0);
                sc[nt][1] = __expf(sc[nt][1] - mn0);
                sc[nt][2] = __expf(sc[nt][2] - mn1);
                sc[nt][3] = __expf(sc[nt][3] - mn1);
                ps0 += sc[nt][0] + sc[nt][1];
                ps1 += sc[nt][2] + sc[nt][3];
            }
            lrow[0] += ps0; lrow[1] += ps1;

#pragma unroll
            for (int j = 0; j < 4; j++) {
                uint32_t ph[4], pl[4];
                ph[0] = pack_hi_split(sc[2 * j][0], sc[2 * j][1], &pl[0]);
                ph[1] = pack_hi_split(sc[2 * j][2], sc[2 * j][3], &pl[1]);
                ph[2] = pack_hi_split(sc[2 * j + 1][0], sc[2 * j + 1][1], &pl[2]);
                ph[3] = pack_hi_split(sc[2 * j + 1][2], sc[2 * j + 1][3], &pl[3]);

#pragma unroll
                for (int p = 0; p < 4; p++) {
                    const uint32_t off =
                        (uint32_t)((p * 16 + lmrow) * ATS + j * 16 + lmk) * 2;
                    uint32_t th[4], tl[4];
                    ldsm_x4(th, pVh + off);
                    ldsm_x4(tl, pVl + off);
                    uint32_t b0h[2] = {th[0], th[2]}, b1h[2] = {th[1], th[3]};
                    uint32_t b0l[2] = {tl[0], tl[2]}, b1l[2] = {tl[1], tl[3]};
                    mma_bf16(o[2 * p],     ph, b0h);
                    mma_bf16(o[2 * p + 1], ph, b1h);
                    mma_bf16(o[2 * p],     pl, b0h);
                    mma_bf16(o[2 * p + 1], pl, b1h);
                    mma_bf16(o[2 * p],     ph, b0l);
                    mma_bf16(o[2 * p + 1], ph, b1l);
                }
            }
        }
    }

    float l0 = lrow[0], l1 = lrow[1];
    l0 += __shfl_xor_sync(0xffffffffu, l0, 1);
    l0 += __shfl_xor_sync(0xffffffffu, l0, 2);
    l1 += __shfl_xor_sync(0xffffffffu, l1, 1);
    l1 += __shfl_xor_sync(0xffffffffu, l1, 2);
    const float inv0 = 1.f / l0, inv1 = 1.f / l1;

    // Fused epilogue: write fp16 hi/lo split of ctx directly ([B,S,D])
#pragma unroll
    for (int d = 0; d < 8; d++) {
        const int n = h * HD + d * 8 + tig * 2;
        {
            const float v0 = o[d][0] * inv0, v1 = o[d][1] * inv0;
            __half h0, h1, e0, e1;
            split2h(v0, h0, e0); split2h(v1, h1, e1);
            const size_t ix = ((size_t)(b_ * SEQ + rowA)) * DIM + n;
            *(__half2*)(ahi + ix) = __halves2half2(h0, h1);
            *(__half2*)(alo + ix) = __halves2half2(e0, e1);
        }
        {
            const float v0 = o[d][2] * inv1, v1 = o[d][3] * inv1;
            __half h0, h1, e0, e1;
            split2h(v0, h0, e0); split2h(v1, h1, e1);
            const size_t ix = ((size_t)(b_ * SEQ + rowB)) * DIM + n;
            *(__half2*)(ahi + ix) = __halves2half2(h0, h1);
            *(__half2*)(alo + ix) = __halves2half2(e0, e1);
        }
    }
}

// ---------------------------------------------------------------------------
extern "C" void kernel_launch(void* const* d_in, const int* in_sizes, int n_in,
                              void* d_out, int out_size) {
    const float* hs  = (const float*)d_in[0];
    // d_in[1] = attention_mask (causal; enforced in-kernel)
    const float* wq  = (const float*)d_in[2];
    const float* wk  = (const float*)d_in[3];
    const float* wv  = (const float*)d_in[4];
    const float* wo  = (const float*)d_in[5];
    const int*   pos = (const int*)d_in[6];
    float* out = (float*)d_out;

    float* qkv;
    __half *ahi, *alo, *whi, *wlo;
    cudaGetSymbolAddress((void**)&qkv, g_qkv);
    cudaGetSymbolAddress((void**)&ahi, g_a_hi);
    cudaGetSymbolAddress((void**)&alo, g_a_lo);
    cudaGetSymbolAddress((void**)&whi, g_wt_hi);
    cudaGetSymbolAddress((void**)&wlo, g_wt_lo);
    float* qp = qkv;
    float* kp = qkv + QKV_OFF;
    float* vp = qkv + 2 * QKV_OFF;

    cudaFuncSetAttribute(gemm_mma_kernel<1>, cudaFuncAttributeMaxDynamicSharedMemorySize, GSMEM);
    cudaFuncSetAttribute(gemm_mma_kernel<0>, cudaFuncAttributeMaxDynamicSharedMemorySize, GSMEM);

    rope_table_kernel<<<(SEQ * 32) / 256, 256>>>();

    const dim3 ggrid3(DIM / 128, (BATCH * SEQ) / 128, 3);
    const dim3 ggrid1(DIM / 128, (BATCH * SEQ) / 128, 1);
    const dim3 wgrid3(DIM / 32, DIM / 32, 3), wgrid1(DIM / 32, DIM / 32, 1), wblk(32, 8);

    convert_act_kernel<<<(BATCH * SEQ * DIM) / 1024, 256>>>(hs, ahi, alo);
    convert_wt_kernel<<<wgrid3, wblk>>>(wq, wk, wv, whi, wlo);
    gemm_mma_kernel<1><<<ggrid3, 256, GSMEM>>>(ahi, alo, whi, wlo, qkv);

    attn_mma_kernel<<<dim3(SEQ / 128, BATCH * NH), 256>>>(qp, kp, vp, pos, ahi, alo);

    convert_wt_kernel<<<wgrid1, wblk>>>(wo, wo, wo, whi, wlo);
    gemm_mma_kernel<0><<<ggrid1, 256, GSMEM>>>(ahi, alo, whi, wlo, out);
}